// round 14
// baseline (speedup 1.0000x reference)
#include <cuda_runtime.h>
#include <cuda_bf16.h>

// SSIM loss, fully fused. (1,3,2048,2048) fp32, VALID 11-tap separable Gaussian
// (sigma=1.5). Output scalar fp32 = 1 - mean(ssim_map) over (3,2038,2038).
//
// v14 = v12 (75.8us) with phase A reorganized: 126 uniform width-11 tasks
// (42 rows x 3 runs, window 21) -> every thread does at most ONE task, cutting
// the critical warp path from 704 to 484 conv-FMAs. Maps {x, y, x^2+y^2, xy}.
// Phase B / tile / epilogue / tail identical to v12.

#define H_DIM 2048
#define W_DIM 2048
#define OUT_DIM 2038
#define TILE 32
#define IN_TILE 42
#define NTHREADS 128
#define HB_STRIDE 33         // 33 slots/row: cols 0..32 (col 32 = harmless pad)
#define GRID_X 64
#define GRID_Y 64
#define NBLOCKS (GRID_X * GRID_Y * 3)

// Normalized gaussian(sigma=1.5, size=11); sum == 1.0f exactly.
#define W0 0.00102841f
#define W1 0.00759878f
#define W2 0.03600077f
#define W3 0.10936067f
#define W4 0.21300553f
#define W5 0.26601168f

__device__ float g_partial[NBLOCKS];

// NOUT 11-tap dot products over an (NOUT+10)-wide window; FFMA-imm weights.
template <int NOUT>
__device__ __forceinline__ void convN(const float* __restrict__ v,
                                      float* __restrict__ acc) {
    const float W[11] = {W0, W1, W2, W3, W4, W5, W4, W3, W2, W1, W0};
    #pragma unroll
    for (int j = 0; j < NOUT; ++j) {
        float a = W0 * v[j];
        #pragma unroll
        for (int t = 1; t < 11; ++t)
            a = fmaf(W[t], v[j + t], a);
        acc[j] = a;
    }
}

__global__ __launch_bounds__(NTHREADS, 6)
void ssim_main_kernel(const float* __restrict__ xin, const float* __restrict__ yin) {
    __shared__ float hb[4][IN_TILE][HB_STRIDE];   // 22.2 KB
    __shared__ float red[4];

    const int tid = threadIdx.x;
    const int gx0 = blockIdx.x * TILE;
    const int gy0 = blockIdx.y * TILE;
    const float* __restrict__ xp = xin + (size_t)blockIdx.z * (H_DIM * W_DIM);
    const float* __restrict__ yp = yin + (size_t)blockIdx.z * (H_DIM * W_DIM);
    const bool interior = (blockIdx.x < GRID_X - 1) && (blockIdx.y < GRID_Y - 1);

    // ---- Phase A: horizontal blur of 4 maps (x, y, x^2+y^2, x*y) ----
    // 42 rows x 3 runs of 11 = 126 uniform tasks; threads 126,127 idle.
    if (tid < IN_TILE * 3) {
        int r  = tid / 3;
        int q  = tid - 3 * r;
        int c0 = q * 11;                 // 0, 11, 22
        int gr = gy0 + r;
        int gc0 = gx0 + c0;
        float xw[21], yw[21], pw[21], acc[11];

        if (interior) {
            const float* xr = xp + (size_t)gr * W_DIM + gc0;
            const float* yr = yp + (size_t)gr * W_DIM + gc0;
            #pragma unroll
            for (int k = 0; k < 21; ++k) xw[k] = __ldg(xr + k);
            #pragma unroll
            for (int k = 0; k < 21; ++k) yw[k] = __ldg(yr + k);
        } else {
            #pragma unroll
            for (int k = 0; k < 21; ++k) {
                int gc = gc0 + k;
                bool ok = (gr < H_DIM) && (gc < W_DIM);
                int idx = gr * W_DIM + gc;
                xw[k] = ok ? __ldg(xp + idx) : 0.0f;
                yw[k] = ok ? __ldg(yp + idx) : 0.0f;
            }
        }

        convN<11>(xw, acc);
        #pragma unroll
        for (int j = 0; j < 11; ++j) hb[0][r][c0 + j] = acc[j];

        convN<11>(yw, acc);
        #pragma unroll
        for (int j = 0; j < 11; ++j) hb[1][r][c0 + j] = acc[j];

        #pragma unroll
        for (int k = 0; k < 21; ++k)
            pw[k] = fmaf(xw[k], xw[k], yw[k] * yw[k]);   // x^2 + y^2
        convN<11>(pw, acc);
        #pragma unroll
        for (int j = 0; j < 11; ++j) hb[2][r][c0 + j] = acc[j];

        #pragma unroll
        for (int k = 0; k < 21; ++k)
            pw[k] = xw[k] * yw[k];                        // x*y
        convN<11>(pw, acc);
        #pragma unroll
        for (int j = 0; j < 11; ++j) hb[3][r][c0 + j] = acc[j];
    }
    __syncthreads();

    // ---- Phase B: vertical blur (8 rows/thread, 4 warps) + SSIM + reduce ----
    const int tx  = tid & 31;          // output column
    const int tg  = tid >> 5;          // row-group 0..3 (8 output rows each)
    const int oyb = tg << 3;

    float acc[4][8];
    #pragma unroll
    for (int m = 0; m < 4; ++m) {
        float v[18];
        #pragma unroll
        for (int k = 0; k < 18; ++k) v[k] = hb[m][oyb + k][tx];
        convN<8>(v, acc[m]);
    }

    const float C1 = 0.01f * 0.01f;
    const float C2 = 0.03f * 0.03f;
    float lsum = 0.0f;
    const int ox = gx0 + tx;
    #pragma unroll
    for (int j = 0; j < 8; ++j) {
        int oy = gy0 + oyb + j;
        if (oy < OUT_DIM && ox < OUT_DIM) {
            float mu1 = acc[0][j], mu2 = acc[1][j];
            float S   = acc[2][j];   // E[x^2 + y^2]
            float Pxy = acc[3][j];   // E[x*y]
            float m11 = mu1 * mu1;
            float m22 = mu2 * mu2;
            float m12 = mu1 * mu2;
            // 2*sigma12 = 2*(Pxy - m12) ; sigma1+sigma2 = S - m11 - m22
            float num = (2.0f * m12 + C1) * (2.0f * (Pxy - m12) + C2);
            float den = (m11 + m22 + C1) * (S - m11 - m22 + C2);
            lsum += __fdividef(num, den);
        }
    }

    #pragma unroll
    for (int off = 16; off > 0; off >>= 1)
        lsum += __shfl_down_sync(0xffffffffu, lsum, off);
    if (tx == 0) red[tg] = lsum;
    __syncthreads();
    if (tid == 0) {
        int bid = (blockIdx.z * GRID_Y + blockIdx.y) * GRID_X + blockIdx.x;
        g_partial[bid] = red[0] + red[1] + red[2] + red[3];
    }
}

// Tail: 1024 threads; fixed-order fp32 partial sums + shuffle tree -> replay-
// deterministic; double only for the final combine.
__global__ __launch_bounds__(1024)
void ssim_final_kernel(float* __restrict__ out) {
    __shared__ double s[32];
    const int t = threadIdx.x;
    const float4* p = reinterpret_cast<const float4*>(g_partial);  // 3072 float4
    float4 a = p[t];
    float4 b = p[t + 1024];
    float4 c = p[t + 2048];
    float fs = ((a.x + a.y) + (a.z + a.w))
             + ((b.x + b.y) + (b.z + b.w))
             + ((c.x + c.y) + (c.z + c.w));
    double sum = (double)fs;
    #pragma unroll
    for (int off = 16; off > 0; off >>= 1)
        sum += __shfl_down_sync(0xffffffffu, sum, off);
    int lane = t & 31, wid = t >> 5;
    if (lane == 0) s[wid] = sum;
    __syncthreads();
    if (wid == 0) {
        double v = s[lane];
        #pragma unroll
        for (int off = 16; off > 0; off >>= 1)
            v += __shfl_down_sync(0xffffffffu, v, off);
        if (lane == 0) {
            double n = 3.0 * (double)OUT_DIM * (double)OUT_DIM;
            out[0] = 1.0f - (float)(v / n);
        }
    }
}

extern "C" void kernel_launch(void* const* d_in, const int* in_sizes, int n_in,
                              void* d_out, int out_size) {
    const float* pred = (const float*)d_in[0];
    const float* targ = (const float*)d_in[1];
    float* out = (float*)d_out;

    dim3 grid(GRID_X, GRID_Y, 3);
    ssim_main_kernel<<<grid, NTHREADS>>>(pred, targ);
    ssim_final_kernel<<<1, 1024>>>(out);
}

// round 15
// speedup vs baseline: 1.1679x; 1.1679x over previous
#include <cuda_runtime.h>
#include <cuda_bf16.h>

// SSIM loss, fully fused. (1,3,2048,2048) fp32, VALID 11-tap separable Gaussian
// (sigma=1.5). Output scalar fp32 = 1 - mean(ssim_map) over (3,2038,2038).
//
// v15 = v12 (75.8us) with the 4 smem map planes paired into 2 float2 planes:
//   hb01 = {blurH(x), blurH(y)},  hb23 = {blurH(x^2+y^2), blurH(x*y)}
// Phase B: 72 LDS.32 -> 36 LDS.64 (half the latency events). Stores 16 STS.64,
// conflict-free via remapped task layout (verified mod-32). Everything else
// (loads, tile 32x32, 128 thr, 6 CTAs/SM, epilogue, tail) identical to v12.

#define H_DIM 2048
#define W_DIM 2048
#define OUT_DIM 2038
#define TILE 32
#define IN_TILE 42
#define NTHREADS 128
#define HB_STRIDE 35         // float2 per row slot; 70 words/row (bank-verified)
#define GRID_X 64
#define GRID_Y 64
#define NBLOCKS (GRID_X * GRID_Y * 3)

// Normalized gaussian(sigma=1.5, size=11); sum == 1.0f exactly.
#define W0 0.00102841f
#define W1 0.00759878f
#define W2 0.03600077f
#define W3 0.10936067f
#define W4 0.21300553f
#define W5 0.26601168f

__device__ float g_partial[NBLOCKS];

// 8 x 11-tap dot products over an 18-wide window; FFMA-imm weights.
__device__ __forceinline__ void conv11(const float* __restrict__ v,
                                       float* __restrict__ acc) {
    const float W[11] = {W0, W1, W2, W3, W4, W5, W4, W3, W2, W1, W0};
    #pragma unroll
    for (int j = 0; j < 8; ++j) {
        float a = W0 * v[j];
        #pragma unroll
        for (int t = 1; t < 11; ++t)
            a = fmaf(W[t], v[j + t], a);
        acc[j] = a;
    }
}

// Same over both lanes of float2 windows.
__device__ __forceinline__ void conv11_f2(const float2* __restrict__ v,
                                          float* __restrict__ aa,
                                          float* __restrict__ ab) {
    const float W[11] = {W0, W1, W2, W3, W4, W5, W4, W3, W2, W1, W0};
    #pragma unroll
    for (int j = 0; j < 8; ++j) {
        float a = W0 * v[j].x;
        float b = W0 * v[j].y;
        #pragma unroll
        for (int t = 1; t < 11; ++t) {
            a = fmaf(W[t], v[j + t].x, a);
            b = fmaf(W[t], v[j + t].y, b);
        }
        aa[j] = a;
        ab[j] = b;
    }
}

__device__ __forceinline__ void load18(const float* __restrict__ p,
                                       float* __restrict__ v) {
    // p is 32B-aligned (offset multiple of 8 floats). 4xLDG.128 + 1xLDG.64.
    #pragma unroll
    for (int k = 0; k < 4; ++k) {
        float4 q = __ldg(reinterpret_cast<const float4*>(p) + k);
        v[4 * k + 0] = q.x; v[4 * k + 1] = q.y;
        v[4 * k + 2] = q.z; v[4 * k + 3] = q.w;
    }
    float2 q2 = __ldg(reinterpret_cast<const float2*>(p) + 8);
    v[16] = q2.x; v[17] = q2.y;
}

__global__ __launch_bounds__(NTHREADS, 6)
void ssim_main_kernel(const float* __restrict__ xin, const float* __restrict__ yin) {
    __shared__ float2 hb01[IN_TILE][HB_STRIDE];   // {E_h[x], E_h[y]}
    __shared__ float2 hb23[IN_TILE][HB_STRIDE];   // {E_h[x^2+y^2], E_h[xy]}
    __shared__ float red[4];

    const int tid = threadIdx.x;
    const int gx0 = blockIdx.x * TILE;
    const int gy0 = blockIdx.y * TILE;
    const float* __restrict__ xp = xin + (size_t)blockIdx.z * (H_DIM * W_DIM);
    const float* __restrict__ yp = yin + (size_t)blockIdx.z * (H_DIM * W_DIM);
    const bool interior = (blockIdx.x < GRID_X - 1) && (blockIdx.y < GRID_Y - 1);

    // ---- Phase A: horizontal blur; 42 rows x 4 runs of 8 cols = 168 tasks.
    // Task->lane map chosen so the 16-lane STS.64 phases are conflict-free:
    //   regular: r = 8*(t>>5) + (t&7), c0 = 8*((t>>3)&3)   (words: 6q+16u+2j)
    //   tail (t>=160): covers rows 40,41 x runs 0..3.
    for (int task = tid; task < IN_TILE * 4; task += NTHREADS) {
        int r, c0;
        if (task < 160) {
            int s = task & 31;
            r  = 8 * (task >> 5) + (s & 7);
            c0 = 8 * (s >> 3);
        } else {
            int e = task - 160;
            r  = 40 + (e >> 2);
            c0 = 8 * (e & 3);
        }
        int gr = gy0 + r;
        int gc0 = gx0 + c0;
        float xw[18], yw[18], pw[18], accA[8], accB[8];

        if (interior) {
            const float* xr = xp + (size_t)gr * W_DIM + gc0;
            const float* yr = yp + (size_t)gr * W_DIM + gc0;
            load18(xr, xw);
            load18(yr, yw);
        } else {
            #pragma unroll
            for (int k = 0; k < 18; ++k) {
                int gc = gc0 + k;
                bool ok = (gr < H_DIM) && (gc < W_DIM);
                int idx = gr * W_DIM + gc;
                xw[k] = ok ? __ldg(xp + idx) : 0.0f;
                yw[k] = ok ? __ldg(yp + idx) : 0.0f;
            }
        }

        conv11(xw, accA);
        conv11(yw, accB);
        #pragma unroll
        for (int j = 0; j < 8; ++j)
            hb01[r][c0 + j] = make_float2(accA[j], accB[j]);

        #pragma unroll
        for (int k = 0; k < 18; ++k)
            pw[k] = fmaf(xw[k], xw[k], yw[k] * yw[k]);   // x^2 + y^2
        conv11(pw, accA);
        #pragma unroll
        for (int k = 0; k < 18; ++k)
            pw[k] = xw[k] * yw[k];                        // x*y
        conv11(pw, accB);
        #pragma unroll
        for (int j = 0; j < 8; ++j)
            hb23[r][c0 + j] = make_float2(accA[j], accB[j]);
    }
    __syncthreads();

    // ---- Phase B: vertical blur (8 rows/thread, 4 warps) + SSIM + reduce ----
    const int tx  = tid & 31;          // output column
    const int tg  = tid >> 5;          // row-group 0..3 (8 output rows each)
    const int oyb = tg << 3;

    float2 v[18];
    float m1[8], m2[8], S[8], Pxy[8];
    #pragma unroll
    for (int k = 0; k < 18; ++k) v[k] = hb01[oyb + k][tx];
    conv11_f2(v, m1, m2);
    #pragma unroll
    for (int k = 0; k < 18; ++k) v[k] = hb23[oyb + k][tx];
    conv11_f2(v, S, Pxy);

    const float C1 = 0.01f * 0.01f;
    const float C2 = 0.03f * 0.03f;
    float lsum = 0.0f;
    const int ox = gx0 + tx;
    #pragma unroll
    for (int j = 0; j < 8; ++j) {
        int oy = gy0 + oyb + j;
        if (oy < OUT_DIM && ox < OUT_DIM) {
            float mu1 = m1[j], mu2 = m2[j];
            float m11 = mu1 * mu1;
            float m22 = mu2 * mu2;
            float m12 = mu1 * mu2;
            // 2*sigma12 = 2*(Pxy - m12) ; sigma1_sq+sigma2_sq = S - m11 - m22
            float num = (2.0f * m12 + C1) * (2.0f * (Pxy[j] - m12) + C2);
            float den = (m11 + m22 + C1) * (S[j] - m11 - m22 + C2);
            lsum += __fdividef(num, den);
        }
    }

    #pragma unroll
    for (int off = 16; off > 0; off >>= 1)
        lsum += __shfl_down_sync(0xffffffffu, lsum, off);
    if (tx == 0) red[tg] = lsum;
    __syncthreads();
    if (tid == 0) {
        int bid = (blockIdx.z * GRID_Y + blockIdx.y) * GRID_X + blockIdx.x;
        g_partial[bid] = red[0] + red[1] + red[2] + red[3];
    }
}

// Tail: 1024 threads; fixed-order fp32 partial sums + shuffle tree -> replay-
// deterministic; double only for the final combine.
__global__ __launch_bounds__(1024)
void ssim_final_kernel(float* __restrict__ out) {
    __shared__ double s[32];
    const int t = threadIdx.x;
    const float4* p = reinterpret_cast<const float4*>(g_partial);  // 3072 float4
    float4 a = p[t];
    float4 b = p[t + 1024];
    float4 c = p[t + 2048];
    float fs = ((a.x + a.y) + (a.z + a.w))
             + ((b.x + b.y) + (b.z + b.w))
             + ((c.x + c.y) + (c.z + c.w));
    double sum = (double)fs;
    #pragma unroll
    for (int off = 16; off > 0; off >>= 1)
        sum += __shfl_down_sync(0xffffffffu, sum, off);
    int lane = t & 31, wid = t >> 5;
    if (lane == 0) s[wid] = sum;
    __syncthreads();
    if (wid == 0) {
        double v2 = s[lane];
        #pragma unroll
        for (int off = 16; off > 0; off >>= 1)
            v2 += __shfl_down_sync(0xffffffffu, v2, off);
        if (lane == 0) {
            double n = 3.0 * (double)OUT_DIM * (double)OUT_DIM;
            out[0] = 1.0f - (float)(v2 / n);
        }
    }
}

extern "C" void kernel_launch(void* const* d_in, const int* in_sizes, int n_in,
                              void* d_out, int out_size) {
    const float* pred = (const float*)d_in[0];
    const float* targ = (const float*)d_in[1];
    float* out = (float*)d_out;

    dim3 grid(GRID_X, GRID_Y, 3);
    ssim_main_kernel<<<grid, NTHREADS>>>(pred, targ);
    ssim_final_kernel<<<1, 1024>>>(out);
}

// round 16
// speedup vs baseline: 1.5043x; 1.2880x over previous
#include <cuda_runtime.h>
#include <cuda_bf16.h>

// SSIM loss, fully fused. (1,3,2048,2048) fp32, VALID 11-tap separable Gaussian
// (sigma=1.5). Output scalar fp32 = 1 - mean(ssim_map) over (3,2038,2038).
//
// v16 = v12 (75.8us) with 192 threads/block:
//  - Phase A: 168 tasks in ONE pass (v12: 2 passes with warps 0-1 double-loaded)
//  - Phase B: 32 rows over 6 warps (6/6/5/5/5/5), lower per-warp register peak
//  - __launch_bounds__(192, 4): same 85-reg budget, same 24 warps/SM
// All proven components unchanged: float4 loads, STS.128 stores (stride 36,
// bank-verified), FFMA-imm convs, float per-block epilogue, 1024-thread tail.

#define H_DIM 2048
#define W_DIM 2048
#define OUT_DIM 2038
#define TILE 32
#define IN_TILE 42
#define NTHREADS 192
#define HB_STRIDE 36
#define GRID_X 64
#define GRID_Y 64
#define NBLOCKS (GRID_X * GRID_Y * 3)

// Normalized gaussian(sigma=1.5, size=11); sum == 1.0f exactly.
#define W0 0.00102841f
#define W1 0.00759878f
#define W2 0.03600077f
#define W3 0.10936067f
#define W4 0.21300553f
#define W5 0.26601168f

__device__ float g_partial[NBLOCKS];

// NOUT 11-tap dot products over an (NOUT+10)-wide window; FFMA-imm weights.
template <int NOUT>
__device__ __forceinline__ void convN(const float* __restrict__ v,
                                      float* __restrict__ acc) {
    const float W[11] = {W0, W1, W2, W3, W4, W5, W4, W3, W2, W1, W0};
    #pragma unroll
    for (int j = 0; j < NOUT; ++j) {
        float a = W0 * v[j];
        #pragma unroll
        for (int t = 1; t < 11; ++t)
            a = fmaf(W[t], v[j + t], a);
        acc[j] = a;
    }
}

__device__ __forceinline__ void load18(const float* __restrict__ p,
                                       float* __restrict__ v) {
    // p is 32B-aligned (offset multiple of 8 floats). 4xLDG.128 + 1xLDG.64.
    #pragma unroll
    for (int k = 0; k < 4; ++k) {
        float4 q = __ldg(reinterpret_cast<const float4*>(p) + k);
        v[4 * k + 0] = q.x; v[4 * k + 1] = q.y;
        v[4 * k + 2] = q.z; v[4 * k + 3] = q.w;
    }
    float2 q2 = __ldg(reinterpret_cast<const float2*>(p) + 8);
    v[16] = q2.x; v[17] = q2.y;
}

__device__ __forceinline__ void store8(float* __restrict__ dst,
                                       const float* __restrict__ a) {
    // dst is 16B-aligned (row*36 and c0 both multiples of 4 floats).
    float4* d4 = reinterpret_cast<float4*>(dst);
    d4[0] = make_float4(a[0], a[1], a[2], a[3]);
    d4[1] = make_float4(a[4], a[5], a[6], a[7]);
}

// Vertical blur + SSIM for NR output rows starting at local row r0.
template <int NR>
__device__ __forceinline__ float ssim_rows(const float hb[4][IN_TILE][HB_STRIDE],
                                           int r0, int tx, int gy0, int ox) {
    float v[NR + 10];
    float acc[4][NR];
    #pragma unroll
    for (int m = 0; m < 4; ++m) {
        #pragma unroll
        for (int k = 0; k < NR + 10; ++k) v[k] = hb[m][r0 + k][tx];
        convN<NR>(v, acc[m]);
    }
    const float C1 = 0.01f * 0.01f;
    const float C2 = 0.03f * 0.03f;
    float lsum = 0.0f;
    #pragma unroll
    for (int j = 0; j < NR; ++j) {
        int oy = gy0 + r0 + j;
        if (oy < OUT_DIM && ox < OUT_DIM) {
            float mu1 = acc[0][j], mu2 = acc[1][j];
            float S   = acc[2][j];   // E[x^2 + y^2]
            float Pxy = acc[3][j];   // E[x*y]
            float m11 = mu1 * mu1;
            float m22 = mu2 * mu2;
            float m12 = mu1 * mu2;
            float num = (2.0f * m12 + C1) * (2.0f * (Pxy - m12) + C2);
            float den = (m11 + m22 + C1) * (S - m11 - m22 + C2);
            lsum += __fdividef(num, den);
        }
    }
    return lsum;
}

__global__ __launch_bounds__(NTHREADS, 4)
void ssim_main_kernel(const float* __restrict__ xin, const float* __restrict__ yin) {
    __shared__ float hb[4][IN_TILE][HB_STRIDE];   // 24.2 KB
    __shared__ float red[6];

    const int tid = threadIdx.x;
    const int gx0 = blockIdx.x * TILE;
    const int gy0 = blockIdx.y * TILE;
    const float* __restrict__ xp = xin + (size_t)blockIdx.z * (H_DIM * W_DIM);
    const float* __restrict__ yp = yin + (size_t)blockIdx.z * (H_DIM * W_DIM);
    const bool interior = (blockIdx.x < GRID_X - 1) && (blockIdx.y < GRID_Y - 1);

    // ---- Phase A: horizontal blur of 4 maps (x, y, x^2+y^2, x*y) ----
    // 42 rows x 4 runs of 8 cols = 168 tasks, ONE pass over 192 threads.
    if (tid < IN_TILE * 4) {
        int r  = tid >> 2;
        int c0 = (tid & 3) << 3;
        int gr = gy0 + r;
        int gc0 = gx0 + c0;
        float xw[18], yw[18], pw[18], acc[8];

        if (interior) {
            const float* xr = xp + (size_t)gr * W_DIM + gc0;
            const float* yr = yp + (size_t)gr * W_DIM + gc0;
            load18(xr, xw);
            load18(yr, yw);
        } else {
            #pragma unroll
            for (int k = 0; k < 18; ++k) {
                int gc = gc0 + k;
                bool ok = (gr < H_DIM) && (gc < W_DIM);
                int idx = gr * W_DIM + gc;
                xw[k] = ok ? __ldg(xp + idx) : 0.0f;
                yw[k] = ok ? __ldg(yp + idx) : 0.0f;
            }
        }

        convN<8>(xw, acc);
        store8(&hb[0][r][c0], acc);

        convN<8>(yw, acc);
        store8(&hb[1][r][c0], acc);

        #pragma unroll
        for (int k = 0; k < 18; ++k)
            pw[k] = fmaf(xw[k], xw[k], yw[k] * yw[k]);   // x^2 + y^2
        convN<8>(pw, acc);
        store8(&hb[2][r][c0], acc);

        #pragma unroll
        for (int k = 0; k < 18; ++k)
            pw[k] = xw[k] * yw[k];                        // x*y
        convN<8>(pw, acc);
        store8(&hb[3][r][c0], acc);
    }
    __syncthreads();

    // ---- Phase B: vertical blur + SSIM; 32 rows over 6 warps: 6/6/5/5/5/5 ----
    const int tx = tid & 31;           // output column
    const int tg = tid >> 5;           // warp id 0..5
    const int ox = gx0 + tx;

    float lsum;
    if (tg < 2) {
        lsum = ssim_rows<6>(hb, tg * 6, tx, gy0, ox);
    } else {
        lsum = ssim_rows<5>(hb, 12 + (tg - 2) * 5, tx, gy0, ox);
    }

    #pragma unroll
    for (int off = 16; off > 0; off >>= 1)
        lsum += __shfl_down_sync(0xffffffffu, lsum, off);
    if (tx == 0) red[tg] = lsum;
    __syncthreads();
    if (tid == 0) {
        float bs = ((red[0] + red[1]) + (red[2] + red[3])) + (red[4] + red[5]);
        int bid = (blockIdx.z * GRID_Y + blockIdx.y) * GRID_X + blockIdx.x;
        g_partial[bid] = bs;
    }
}

// Tail: 1024 threads; fixed-order fp32 partial sums + shuffle tree -> replay-
// deterministic; double only for the final combine.
__global__ __launch_bounds__(1024)
void ssim_final_kernel(float* __restrict__ out) {
    __shared__ double s[32];
    const int t = threadIdx.x;
    const float4* p = reinterpret_cast<const float4*>(g_partial);  // 3072 float4
    float4 a = p[t];
    float4 b = p[t + 1024];
    float4 c = p[t + 2048];
    float fs = ((a.x + a.y) + (a.z + a.w))
             + ((b.x + b.y) + (b.z + b.w))
             + ((c.x + c.y) + (c.z + c.w));
    double sum = (double)fs;
    #pragma unroll
    for (int off = 16; off > 0; off >>= 1)
        sum += __shfl_down_sync(0xffffffffu, sum, off);
    int lane = t & 31, wid = t >> 5;
    if (lane == 0) s[wid] = sum;
    __syncthreads();
    if (wid == 0) {
        double v = s[lane];
        #pragma unroll
        for (int off = 16; off > 0; off >>= 1)
            v += __shfl_down_sync(0xffffffffu, v, off);
        if (lane == 0) {
            double n = 3.0 * (double)OUT_DIM * (double)OUT_DIM;
            out[0] = 1.0f - (float)(v / n);
        }
    }
}

extern "C" void kernel_launch(void* const* d_in, const int* in_sizes, int n_in,
                              void* d_out, int out_size) {
    const float* pred = (const float*)d_in[0];
    const float* targ = (const float*)d_in[1];
    float* out = (float*)d_out;

    dim3 grid(GRID_X, GRID_Y, 3);
    ssim_main_kernel<<<grid, NTHREADS>>>(pred, targ);
    ssim_final_kernel<<<1, 1024>>>(out);
}

// round 17
// speedup vs baseline: 1.5914x; 1.0579x over previous
#include <cuda_runtime.h>
#include <cuda_bf16.h>

// SSIM loss, fully fused. (1,3,2048,2048) fp32, VALID 11-tap separable Gaussian
// (sigma=1.5). Output scalar fp32 = 1 - mean(ssim_map) over (3,2038,2038).
//
// v17 = the fair tall-tile test: TILE_H=54 (IN_H=64), 256 threads.
//  - Phase A: 256 tasks = exactly one per thread (v12 critical warp did 2)
//  - Phase B: 54 rows over 8 warps (7x6 + 6x2), NR<=7 -> lower reg peak than v12
//  - launch_bounds(256,3): same 85-reg budget, same 24 warps/SM as v12
//  - all proven components: float4 loads, STS.128 stride-36, FFMA-imm convs,
//    plain float per-block epilogue, 1024-thread tail (padded g_partial)

#define H_DIM 2048
#define W_DIM 2048
#define OUT_DIM 2038
#define TILE_W 32
#define TILE_H 54
#define IN_H 64
#define NTHREADS 256
#define HB_STRIDE 36
#define GRID_X 64
#define GRID_Y 38            // 38*54 = 2052 >= 2038
#define NBLOCKS_PAD 12288    // padded; unwritten slots stay 0.0 forever

// Normalized gaussian(sigma=1.5, size=11); sum == 1.0f exactly.
#define W0 0.00102841f
#define W1 0.00759878f
#define W2 0.03600077f
#define W3 0.10936067f
#define W4 0.21300553f
#define W5 0.26601168f

__device__ float g_partial[NBLOCKS_PAD];

// NOUT 11-tap dot products over an (NOUT+10)-wide window; FFMA-imm weights.
template <int NOUT>
__device__ __forceinline__ void convN(const float* __restrict__ v,
                                      float* __restrict__ acc) {
    const float W[11] = {W0, W1, W2, W3, W4, W5, W4, W3, W2, W1, W0};
    #pragma unroll
    for (int j = 0; j < NOUT; ++j) {
        float a = W0 * v[j];
        #pragma unroll
        for (int t = 1; t < 11; ++t)
            a = fmaf(W[t], v[j + t], a);
        acc[j] = a;
    }
}

__device__ __forceinline__ void load18(const float* __restrict__ p,
                                       float* __restrict__ v) {
    // p is 32B-aligned (offset multiple of 8 floats). 4xLDG.128 + 1xLDG.64.
    #pragma unroll
    for (int k = 0; k < 4; ++k) {
        float4 q = __ldg(reinterpret_cast<const float4*>(p) + k);
        v[4 * k + 0] = q.x; v[4 * k + 1] = q.y;
        v[4 * k + 2] = q.z; v[4 * k + 3] = q.w;
    }
    float2 q2 = __ldg(reinterpret_cast<const float2*>(p) + 8);
    v[16] = q2.x; v[17] = q2.y;
}

__device__ __forceinline__ void store8(float* __restrict__ dst,
                                       const float* __restrict__ a) {
    // dst is 16B-aligned (row*36 and c0 both multiples of 4 floats).
    float4* d4 = reinterpret_cast<float4*>(dst);
    d4[0] = make_float4(a[0], a[1], a[2], a[3]);
    d4[1] = make_float4(a[4], a[5], a[6], a[7]);
}

// Vertical blur + SSIM for NR output rows starting at local row r0.
template <int NR>
__device__ __forceinline__ float ssim_rows(const float hb[4][IN_H][HB_STRIDE],
                                           int r0, int tx, int gy0, int ox) {
    float v[NR + 10];
    float acc[4][NR];
    #pragma unroll
    for (int m = 0; m < 4; ++m) {
        #pragma unroll
        for (int k = 0; k < NR + 10; ++k) v[k] = hb[m][r0 + k][tx];
        convN<NR>(v, acc[m]);
    }
    const float C1 = 0.01f * 0.01f;
    const float C2 = 0.03f * 0.03f;
    float lsum = 0.0f;
    #pragma unroll
    for (int j = 0; j < NR; ++j) {
        int oy = gy0 + r0 + j;
        if (oy < OUT_DIM && ox < OUT_DIM) {
            float mu1 = acc[0][j], mu2 = acc[1][j];
            float S   = acc[2][j];   // E[x^2 + y^2]
            float Pxy = acc[3][j];   // E[x*y]
            float m11 = mu1 * mu1;
            float m22 = mu2 * mu2;
            float m12 = mu1 * mu2;
            float num = (2.0f * m12 + C1) * (2.0f * (Pxy - m12) + C2);
            float den = (m11 + m22 + C1) * (S - m11 - m22 + C2);
            lsum += __fdividef(num, den);
        }
    }
    return lsum;
}

__global__ __launch_bounds__(NTHREADS, 3)
void ssim_main_kernel(const float* __restrict__ xin, const float* __restrict__ yin) {
    __shared__ float hb[4][IN_H][HB_STRIDE];   // 36.9 KB
    __shared__ float red[8];

    const int tid = threadIdx.x;
    const int gx0 = blockIdx.x * TILE_W;
    const int gy0 = blockIdx.y * TILE_H;
    const float* __restrict__ xp = xin + (size_t)blockIdx.z * (H_DIM * W_DIM);
    const float* __restrict__ yp = yin + (size_t)blockIdx.z * (H_DIM * W_DIM);
    const bool interior = (blockIdx.x < GRID_X - 1) && (gy0 + IN_H <= H_DIM);

    // ---- Phase A: horizontal blur of 4 maps (x, y, x^2+y^2, x*y) ----
    // 64 rows x 4 runs of 8 cols = 256 tasks = exactly one per thread.
    {
        int r  = tid >> 2;
        int c0 = (tid & 3) << 3;
        int gr = gy0 + r;
        int gc0 = gx0 + c0;
        float xw[18], yw[18], pw[18], acc[8];

        if (interior) {
            const float* xr = xp + (size_t)gr * W_DIM + gc0;
            const float* yr = yp + (size_t)gr * W_DIM + gc0;
            load18(xr, xw);
            load18(yr, yw);
        } else {
            #pragma unroll
            for (int k = 0; k < 18; ++k) {
                int gc = gc0 + k;
                bool ok = (gr < H_DIM) && (gc < W_DIM);
                int idx = gr * W_DIM + gc;
                xw[k] = ok ? __ldg(xp + idx) : 0.0f;
                yw[k] = ok ? __ldg(yp + idx) : 0.0f;
            }
        }

        convN<8>(xw, acc);
        store8(&hb[0][r][c0], acc);

        convN<8>(yw, acc);
        store8(&hb[1][r][c0], acc);

        #pragma unroll
        for (int k = 0; k < 18; ++k)
            pw[k] = fmaf(xw[k], xw[k], yw[k] * yw[k]);   // x^2 + y^2
        convN<8>(pw, acc);
        store8(&hb[2][r][c0], acc);

        #pragma unroll
        for (int k = 0; k < 18; ++k)
            pw[k] = xw[k] * yw[k];                        // x*y
        convN<8>(pw, acc);
        store8(&hb[3][r][c0], acc);
    }
    __syncthreads();

    // ---- Phase B: vertical blur + SSIM; 54 rows over 8 warps: 7x6 + 6x2 ----
    const int tx = tid & 31;           // output column
    const int tg = tid >> 5;           // warp id 0..7
    const int ox = gx0 + tx;

    float lsum;
    if (tg < 6) {
        lsum = ssim_rows<7>(hb, tg * 7, tx, gy0, ox);
    } else {
        lsum = ssim_rows<6>(hb, 42 + (tg - 6) * 6, tx, gy0, ox);
    }

    #pragma unroll
    for (int off = 16; off > 0; off >>= 1)
        lsum += __shfl_down_sync(0xffffffffu, lsum, off);
    if (tx == 0) red[tg] = lsum;
    __syncthreads();
    if (tid == 0) {
        float bs = ((red[0] + red[1]) + (red[2] + red[3]))
                 + ((red[4] + red[5]) + (red[6] + red[7]));
        int bid = (blockIdx.z * GRID_Y + blockIdx.y) * GRID_X + blockIdx.x;
        g_partial[bid] = bs;
    }
}

// Tail: 1024 threads; fixed-order fp32 partial sums + shuffle tree -> replay-
// deterministic; double only for the final combine. Padded array: unwritten
// slots are always 0.
__global__ __launch_bounds__(1024)
void ssim_final_kernel(float* __restrict__ out) {
    __shared__ double s[32];
    const int t = threadIdx.x;
    const float4* p = reinterpret_cast<const float4*>(g_partial);  // 3072 float4
    float4 a = p[t];
    float4 b = p[t + 1024];
    float4 c = p[t + 2048];
    float fs = ((a.x + a.y) + (a.z + a.w))
             + ((b.x + b.y) + (b.z + b.w))
             + ((c.x + c.y) + (c.z + c.w));
    double sum = (double)fs;
    #pragma unroll
    for (int off = 16; off > 0; off >>= 1)
        sum += __shfl_down_sync(0xffffffffu, sum, off);
    int lane = t & 31, wid = t >> 5;
    if (lane == 0) s[wid] = sum;
    __syncthreads();
    if (wid == 0) {
        double v = s[lane];
        #pragma unroll
        for (int off = 16; off > 0; off >>= 1)
            v += __shfl_down_sync(0xffffffffu, v, off);
        if (lane == 0) {
            double n = 3.0 * (double)OUT_DIM * (double)OUT_DIM;
            out[0] = 1.0f - (float)(v / n);
        }
    }
}

extern "C" void kernel_launch(void* const* d_in, const int* in_sizes, int n_in,
                              void* d_out, int out_size) {
    const float* pred = (const float*)d_in[0];
    const float* targ = (const float*)d_in[1];
    float* out = (float*)d_out;

    dim3 grid(GRID_X, GRID_Y, 3);
    ssim_main_kernel<<<grid, NTHREADS>>>(pred, targ);
    ssim_final_kernel<<<1, 1024>>>(out);
}